// round 17
// baseline (speedup 1.0000x reference)
#include <cuda_runtime.h>
#include <cuda_fp16.h>
#include <mma.h>
#include <math.h>
#include <stdint.h>

using namespace nvcuda;

#define NV      6144
#define NFEAT   128
#define NHID    64
#define NHEAD   4
#define NCLASS  16
#define CAP     256
#define ALPHA   0.2f
#define NEGV    (-1e10f)
#define LDA     136
#define LDB     72
#define ROWS_PER_OUT_BLOCK 8
#define ROWS_PER_ATTN_BLOCK 4

// ---------------- device scratch ----------------
__device__ __half g_featH[(size_t)NV * NFEAT];
__device__ __half g_WeffH[NFEAT * NHEAD * NHID];
__device__ __half g_Hh[(size_t)NV * NHEAD * NHID];
__device__ float  g_s[NHEAD * NV];
__device__ float  g_t[NHEAD * NV];
__device__ int    g_nbr[(size_t)NV * CAP];
__device__ int    g_cnt[NV];
__device__ float  g_H2[(size_t)NV * NCLASS];
__device__ float  g_s2[NV];
__device__ float  g_t2[NV];

__device__ __forceinline__ float lrelu(float x) { return x > 0.f ? x : ALPHA * x; }
__device__ __forceinline__ float eluf(float x)  { return x > 0.f ? x : (__expf(x) - 1.f); }
__device__ __forceinline__ unsigned smem_u32(const void* p) {
    return (unsigned)__cvta_generic_to_shared(p);
}

// ---------------- K0: prep — fold W0 -> fp16, convert feat -> fp16 ----------------
__global__ void __launch_bounds__(256) k_prep(const float* __restrict__ W0,
                                              const float* __restrict__ feat) {
    int b = blockIdx.x, tid = threadIdx.x;
    if (b < 128) {
        int linear = b * 256 + tid;
        int k = linear >> 8, C = linear & 255;
        int h = C >> 6, c = C & 63;
        const float* base = W0 + (size_t)h * 512 * 64;
        float v = 0.f;
#pragma unroll
        for (int t = 0; t < 4; t++) v += base[(t * 128 + k) * 64 + c];
        g_WeffH[k * 256 + C] = __float2half_rn(v);
    } else {
        int fb = b - 128;
        const float4* src = reinterpret_cast<const float4*>(feat) + (size_t)fb * 512 + tid * 2;
        float4 v0 = src[0], v1 = src[1];
        __half2 h0 = __floats2half2_rn(v0.x, v0.y);
        __half2 h1 = __floats2half2_rn(v0.z, v0.w);
        __half2 h2 = __floats2half2_rn(v1.x, v1.y);
        __half2 h3 = __floats2half2_rn(v1.z, v1.w);
        uint4 st;
        st.x = *reinterpret_cast<unsigned*>(&h0);
        st.y = *reinterpret_cast<unsigned*>(&h1);
        st.z = *reinterpret_cast<unsigned*>(&h2);
        st.w = *reinterpret_cast<unsigned*>(&h3);
        reinterpret_cast<uint4*>(g_featH)[(size_t)fb * 256 + tid] = st;
    }
}

// ---------------- K1: tensor-core GEMM + fused s/t ----------------
__global__ void __launch_bounds__(256) k_gemm(const float* __restrict__ a1g,
                                              const float* __restrict__ a2g) {
    __shared__ __align__(16) __half AsH[64 * LDA];
    __shared__ __align__(16) __half BsH[128 * LDB];
    float* Cs = reinterpret_cast<float*>(AsH);
    int tid = threadIdx.x;
    int head = blockIdx.x & 3;
    int row0 = (blockIdx.x >> 2) * 64;

    const uint4* fh4 = reinterpret_cast<const uint4*>(g_featH);
#pragma unroll
    for (int it = 0; it < 4; it++) {
        int idx = it * 256 + tid;
        int r = idx >> 4, c8 = idx & 15;
        uint4 v = __ldg(&fh4[(size_t)(row0 + r) * 16 + c8]);
        *reinterpret_cast<uint4*>(&AsH[r * LDA + c8 * 8]) = v;
    }
#pragma unroll
    for (int it = 0; it < 4; it++) {
        int idx = it * 256 + tid;
        int k = idx >> 3, c8 = idx & 7;
        uint4 v = *reinterpret_cast<const uint4*>(&g_WeffH[k * 256 + head * 64 + c8 * 8]);
        *reinterpret_cast<uint4*>(&BsH[k * LDB + c8 * 8]) = v;
    }
    __syncthreads();

    int warp = tid >> 5;
    int wr = (warp >> 1) * 16;
    int wc = (warp & 1) * 32;
    wmma::fragment<wmma::accumulator, 16, 16, 16, float> c0, c1;
    wmma::fill_fragment(c0, 0.f);
    wmma::fill_fragment(c1, 0.f);
#pragma unroll
    for (int k0 = 0; k0 < 128; k0 += 16) {
        wmma::fragment<wmma::matrix_a, 16, 16, 16, __half, wmma::row_major> a;
        wmma::fragment<wmma::matrix_b, 16, 16, 16, __half, wmma::row_major> b0, b1;
        wmma::load_matrix_sync(a, &AsH[wr * LDA + k0], LDA);
        wmma::load_matrix_sync(b0, &BsH[k0 * LDB + wc], LDB);
        wmma::load_matrix_sync(b1, &BsH[k0 * LDB + wc + 16], LDB);
        wmma::mma_sync(c0, a, b0, c0);
        wmma::mma_sync(c1, a, b1, c1);
    }
    __syncthreads();
    wmma::store_matrix_sync(&Cs[wr * 64 + wc], c0, 64, wmma::mem_row_major);
    wmma::store_matrix_sync(&Cs[wr * 64 + wc + 16], c1, 64, wmma::mem_row_major);
    __syncthreads();

    int r = tid >> 2, q = tid & 3;
    const float* crow = &Cs[r * 64 + q * 16];
    float sa = 0.f, sb = 0.f;
    __half hbuf[16];
#pragma unroll
    for (int c = 0; c < 16; c++) {
        float v = crow[c];
        hbuf[c] = __float2half_rn(v);
        sa += v * __ldg(&a1g[head * 64 + q * 16 + c]);
        sb += v * __ldg(&a2g[head * 64 + q * 16 + c]);
    }
    uint4* dst = reinterpret_cast<uint4*>(&g_Hh[(size_t)(row0 + r) * 256 + head * 64 + q * 16]);
    const uint4* src = reinterpret_cast<const uint4*>(hbuf);
    dst[0] = src[0];
    dst[1] = src[1];
    sa += __shfl_down_sync(0xffffffffu, sa, 2, 4);
    sa += __shfl_down_sync(0xffffffffu, sa, 1, 4);
    sb += __shfl_down_sync(0xffffffffu, sb, 2, 4);
    sb += __shfl_down_sync(0xffffffffu, sb, 1, 4);
    if (q == 0) {
        g_s[head * NV + row0 + r] = sa;
        g_t[head * NV + row0 + r] = sb;
    }
}

// ---------------- K2: pipelined adj-scan (cp.async half-prefetch) + attention + out-proj ----------------
__global__ void __launch_bounds__(256) k_attn_hidden(const float* __restrict__ adj,
                                                     const float* __restrict__ Wout,
                                                     const float* __restrict__ a1o,
                                                     const float* __restrict__ a2o) {
    int tid = threadIdx.x;
    int warp = tid >> 5, lane = tid & 31;
    __shared__ __align__(16) uint4 abuf[768];          // 12KB prefetch buffer (chunks 0..2)
    __shared__ int    s_idx[CAP];
    __shared__ float  s_w[NHEAD][CAP];
    __shared__ float  s_stat[NHEAD];
    __shared__ float  partF[8][256];                   // aliased: red + part2 reuse this
    __shared__ float  s_x2[256];
    __shared__ int    wsum[8];
    __shared__ int    s_cnt;
    float* red = &partF[0][0];
    float* part2 = &partF[0][0];                       // used after partF consumed (post-sync)

    int base_row = blockIdx.x * ROWS_PER_ATTN_BLOCK;

    // prologue: prefetch chunks 0..2 of first row
    {
        const char* src = (const char*)adj + (size_t)base_row * NV * 4;
#pragma unroll
        for (int it = 0; it < 3; it++) {
            unsigned d = smem_u32(&abuf[it * 256 + tid]);
            asm volatile("cp.async.cg.shared.global [%0], [%1], 16;"
                         :: "r"(d), "l"(src + (size_t)(it * 256 + tid) * 16) : "memory");
        }
        asm volatile("cp.async.commit_group;" ::: "memory");
    }

    for (int rr = 0; rr < ROWS_PER_ATTN_BLOCK; rr++) {
        int row = base_row + rr;
        asm volatile("cp.async.wait_group 0;" ::: "memory");
        __syncthreads();

        // ---- scan: chunks 3..5 direct (streaming), chunks 0..2 from prefetch buffer ----
        {
            const uint4* a4 = reinterpret_cast<const uint4*>(adj) + (size_t)row * (NV / 4);
            uint4 v3 = __ldcs(&a4[3 * 256 + tid]);
            uint4 v4 = __ldcs(&a4[4 * 256 + tid]);
            uint4 v5 = __ldcs(&a4[5 * 256 + tid]);
            uint4 v0 = abuf[0 * 256 + tid];
            uint4 v1 = abuf[1 * 256 + tid];
            uint4 v2 = abuf[2 * 256 + tid];
            unsigned mask = 0;
            if (v0.x) mask |= 1u << 0;  if (v0.y) mask |= 1u << 1;
            if (v0.z) mask |= 1u << 2;  if (v0.w) mask |= 1u << 3;
            if (v1.x) mask |= 1u << 4;  if (v1.y) mask |= 1u << 5;
            if (v1.z) mask |= 1u << 6;  if (v1.w) mask |= 1u << 7;
            if (v2.x) mask |= 1u << 8;  if (v2.y) mask |= 1u << 9;
            if (v2.z) mask |= 1u << 10; if (v2.w) mask |= 1u << 11;
            if (v3.x) mask |= 1u << 12; if (v3.y) mask |= 1u << 13;
            if (v3.z) mask |= 1u << 14; if (v3.w) mask |= 1u << 15;
            if (v4.x) mask |= 1u << 16; if (v4.y) mask |= 1u << 17;
            if (v4.z) mask |= 1u << 18; if (v4.w) mask |= 1u << 19;
            if (v5.x) mask |= 1u << 20; if (v5.y) mask |= 1u << 21;
            if (v5.z) mask |= 1u << 22; if (v5.w) mask |= 1u << 23;
            int c = __popc(mask);
            int incl = c;
#pragma unroll
            for (int o = 1; o < 32; o <<= 1) {
                int n = __shfl_up_sync(0xffffffffu, incl, o);
                if (lane >= o) incl += n;
            }
            if (lane == 31) wsum[warp] = incl;
            __syncthreads();          // abuf fully consumed past this point
            int base = 0;
#pragma unroll
            for (int w = 0; w < 8; w++) if (w < warp) base += wsum[w];
            int pos = base + incl - c;
            while (mask) {
                int b = __ffs(mask) - 1;
                mask &= mask - 1;
                if (pos < CAP) s_idx[pos] = (b >> 2) * 1024 + tid * 4 + (b & 3);
                pos++;
            }
            if (tid == 255) {
                int total = base + incl;
                s_cnt = total;
                g_cnt[row] = total;
            }
        }
        __syncthreads();

        // ---- prefetch next row's chunks 0..2 (overlaps with attention below) ----
        if (rr + 1 < ROWS_PER_ATTN_BLOCK) {
            const char* src = (const char*)adj + (size_t)(row + 1) * NV * 4;
#pragma unroll
            for (int it = 0; it < 3; it++) {
                unsigned d = smem_u32(&abuf[it * 256 + tid]);
                asm volatile("cp.async.cg.shared.global [%0], [%1], 16;"
                             :: "r"(d), "l"(src + (size_t)(it * 256 + tid) * 16) : "memory");
            }
            asm volatile("cp.async.commit_group;" ::: "memory");
        }

        int cnt = s_cnt;
        bool sparse = (cnt > 0 && cnt <= CAP);
        if (sparse)
            for (int k = tid; k < cnt; k += 256) g_nbr[(size_t)row * CAP + k] = s_idx[k];

        if (sparse) {
            if (warp < 4) {
                float s_i = g_s[warp * NV + row];
                const float* tv = g_t + warp * NV;
                float mx = -INFINITY;
                for (int k = lane; k < cnt; k += 32) {
                    float lv = lrelu(s_i + __ldg(&tv[s_idx[k]]));
                    s_w[warp][k] = lv;
                    mx = fmaxf(mx, lv);
                }
#pragma unroll
                for (int o = 16; o > 0; o >>= 1) mx = fmaxf(mx, __shfl_xor_sync(0xffffffffu, mx, o));
                float sum = 0.f;
                for (int k = lane; k < cnt; k += 32) {
                    float e = __expf(s_w[warp][k] - mx);
                    s_w[warp][k] = e;
                    sum += e;
                }
#pragma unroll
                for (int o = 16; o > 0; o >>= 1) sum += __shfl_xor_sync(0xffffffffu, sum, o);
                if (lane == 0) s_stat[warp] = sum;
            }
            __syncthreads();
            int q = tid >> 5;
            int c8 = lane;
            int hh = c8 >> 3;
            float a0 = 0.f, a1 = 0.f, a2 = 0.f, a3 = 0.f, a4 = 0.f, a5 = 0.f, a6 = 0.f, a7 = 0.f;
            const uint4* hrow4 = reinterpret_cast<const uint4*>(g_Hh);
            int k = q;
            for (; k + 8 < cnt; k += 16) {
                float w0 = s_w[hh][k], w1 = s_w[hh][k + 8];
                uint4 r0 = __ldg(&hrow4[(size_t)s_idx[k] * 32 + c8]);
                uint4 r1 = __ldg(&hrow4[(size_t)s_idx[k + 8] * 32 + c8]);
                float2 f0 = __half22float2(*reinterpret_cast<__half2*>(&r0.x));
                float2 f1 = __half22float2(*reinterpret_cast<__half2*>(&r0.y));
                float2 f2 = __half22float2(*reinterpret_cast<__half2*>(&r0.z));
                float2 f3 = __half22float2(*reinterpret_cast<__half2*>(&r0.w));
                a0 += w0 * f0.x; a1 += w0 * f0.y; a2 += w0 * f1.x; a3 += w0 * f1.y;
                a4 += w0 * f2.x; a5 += w0 * f2.y; a6 += w0 * f3.x; a7 += w0 * f3.y;
                f0 = __half22float2(*reinterpret_cast<__half2*>(&r1.x));
                f1 = __half22float2(*reinterpret_cast<__half2*>(&r1.y));
                f2 = __half22float2(*reinterpret_cast<__half2*>(&r1.z));
                f3 = __half22float2(*reinterpret_cast<__half2*>(&r1.w));
                a0 += w1 * f0.x; a1 += w1 * f0.y; a2 += w1 * f1.x; a3 += w1 * f1.y;
                a4 += w1 * f2.x; a5 += w1 * f2.y; a6 += w1 * f3.x; a7 += w1 * f3.y;
            }
            for (; k < cnt; k += 8) {
                float w = s_w[hh][k];
                uint4 r0 = __ldg(&hrow4[(size_t)s_idx[k] * 32 + c8]);
                float2 f0 = __half22float2(*reinterpret_cast<__half2*>(&r0.x));
                float2 f1 = __half22float2(*reinterpret_cast<__half2*>(&r0.y));
                float2 f2 = __half22float2(*reinterpret_cast<__half2*>(&r0.z));
                float2 f3 = __half22float2(*reinterpret_cast<__half2*>(&r0.w));
                a0 += w * f0.x; a1 += w * f0.y; a2 += w * f1.x; a3 += w * f1.y;
                a4 += w * f2.x; a5 += w * f2.y; a6 += w * f3.x; a7 += w * f3.y;
            }
            int cb = c8 * 8;
            partF[q][cb + 0] = a0; partF[q][cb + 1] = a1; partF[q][cb + 2] = a2; partF[q][cb + 3] = a3;
            partF[q][cb + 4] = a4; partF[q][cb + 5] = a5; partF[q][cb + 6] = a6; partF[q][cb + 7] = a7;
            __syncthreads();
            {
                float v = partF[0][tid] + partF[1][tid] + partF[2][tid] + partF[3][tid]
                        + partF[4][tid] + partF[5][tid] + partF[6][tid] + partF[7][tid];
                s_x2[tid] = eluf(v / s_stat[tid >> 6]);
            }
        } else {
            int g = tid >> 6, l = tid & 63;
            const float* arow = adj + (size_t)row * NV;
            float s_i = g_s[g * NV + row];
            const float* tvec = g_t + g * NV;
            float mx = -INFINITY;
            for (int j = l; j < NV; j += 64) {
                float lv = lrelu(s_i + tvec[j]);
                if (__ldcs(&arow[j]) == 0.f) lv += NEGV;
                mx = fmaxf(mx, lv);
            }
            red[tid] = mx; __syncthreads();
            if (l < 32) {
                float m = fmaxf(red[tid], red[tid + 32]);
#pragma unroll
                for (int o = 16; o > 0; o >>= 1) m = fmaxf(m, __shfl_xor_sync(0xffffffffu, m, o));
                if (l == 0) s_stat[g] = m;
            }
            __syncthreads();
            mx = s_stat[g];
            float sum = 0.f;
            for (int j = l; j < NV; j += 64) {
                float lv = lrelu(s_i + tvec[j]);
                if (__ldcs(&arow[j]) == 0.f) lv += NEGV;
                sum += __expf(lv - mx);
            }
            __syncthreads();
            red[tid] = sum; __syncthreads();
            if (l < 32) {
                float s = red[tid] + red[tid + 32];
#pragma unroll
                for (int o = 16; o > 0; o >>= 1) s += __shfl_xor_sync(0xffffffffu, s, o);
                if (l == 0) s_stat[g] = s;
            }
            __syncthreads();
            float S = s_stat[g];
            float acc = 0.f;
            const __half* hb = g_Hh + g * 64 + l;
            for (int j = 0; j < NV; j++) {
                float lv = lrelu(s_i + tvec[j]);
                if (arow[j] == 0.f) lv += NEGV;
                acc += __expf(lv - mx) * __half2float(hb[(size_t)j * 256]);
            }
            __syncthreads();
            s_x2[g * 64 + l] = eluf(acc / S);
        }
        __syncthreads();

        // ---- fused out-projection (part2 aliases partF; partF already consumed) ----
        {
            int c = tid & 15, kq = tid >> 4;
            float acc = 0.f;
#pragma unroll
            for (int k = 0; k < 16; k++)
                acc += s_x2[kq * 16 + k] * __ldg(&Wout[(kq * 16 + k) * 16 + c]);
            part2[kq * 16 + c] = acc;
        }
        __syncthreads();
        if (tid < 16) {
            float h = 0.f;
#pragma unroll
            for (int w = 0; w < 16; w++) h += part2[w * 16 + tid];
            g_H2[(size_t)row * 16 + tid] = h;
            float sa = h * __ldg(&a1o[tid]), sb = h * __ldg(&a2o[tid]);
#pragma unroll
            for (int o = 8; o > 0; o >>= 1) {
                sa += __shfl_xor_sync(0xffffu, sa, o, 16);
                sb += __shfl_xor_sync(0xffffu, sb, o, 16);
            }
            if (tid == 0) { g_s2[row] = sa; g_t2[row] = sb; }
        }
        __syncthreads();   // all shared buffers free before next row
    }
}

// ---------------- K3: output attention, warp-per-row, 8 rows/block ----------------
__global__ void __launch_bounds__(256) k_attn_out(const float* __restrict__ adj, float* __restrict__ out) {
    __shared__ float s_w[ROWS_PER_OUT_BLOCK][CAP];
    __shared__ int   s_ix[ROWS_PER_OUT_BLOCK][CAP];
    __shared__ float part[ROWS_PER_OUT_BLOCK][8][16];
    int w = threadIdx.x >> 5, lane = threadIdx.x & 31;
    int row = blockIdx.x * ROWS_PER_OUT_BLOCK + w;
    int cnt = g_cnt[row];
    float s_i = g_s2[row];
    bool sparse = (cnt > 0 && cnt <= CAP);

    if (sparse) {
        const int* nb = g_nbr + (size_t)row * CAP;
        float mx = -INFINITY;
        for (int k = lane; k < cnt; k += 32) {
            int ix = __ldg(&nb[k]);
            s_ix[w][k] = ix;
            float lv = lrelu(s_i + __ldg(&g_t2[ix]));
            s_w[w][k] = lv;
            mx = fmaxf(mx, lv);
        }
#pragma unroll
        for (int o = 16; o > 0; o >>= 1) mx = fmaxf(mx, __shfl_xor_sync(0xffffffffu, mx, o));
        float sum = 0.f;
        for (int k = lane; k < cnt; k += 32) {
            float e = __expf(s_w[w][k] - mx);
            s_w[w][k] = e;
            sum += e;
        }
#pragma unroll
        for (int o = 16; o > 0; o >>= 1) sum += __shfl_xor_sync(0xffffffffu, sum, o);
        __syncwarp();
        int ph = lane >> 2, c4 = lane & 3;
        const float4* h24 = reinterpret_cast<const float4*>(g_H2);
        float4 acc = make_float4(0.f, 0.f, 0.f, 0.f);
        int k = ph;
        for (; k + 8 < cnt; k += 16) {
            float w0 = s_w[w][k], w1 = s_w[w][k + 8];
            float4 v0 = __ldg(&h24[(size_t)s_ix[w][k] * 4 + c4]);
            float4 v1 = __ldg(&h24[(size_t)s_ix[w][k + 8] * 4 + c4]);
            acc.x += w0 * v0.x + w1 * v1.x;
            acc.y += w0 * v0.y + w1 * v1.y;
            acc.z += w0 * v0.z + w1 * v1.z;
            acc.w += w0 * v0.w + w1 * v1.w;
        }
        for (; k < cnt; k += 8) {
            float w0 = s_w[w][k];
            float4 v0 = __ldg(&h24[(size_t)s_ix[w][k] * 4 + c4]);
            acc.x += w0 * v0.x; acc.y += w0 * v0.y; acc.z += w0 * v0.z; acc.w += w0 * v0.w;
        }
        *reinterpret_cast<float4*>(&part[w][ph][c4 * 4]) = acc;
        __syncwarp();
        float a = 0.f;
        if (lane < 16) {
#pragma unroll
            for (int p = 0; p < 8; p++) a += part[w][p][lane];
        }
        float v = eluf(a / sum);
        float m16 = v;
#pragma unroll
        for (int o = 8; o > 0; o >>= 1) m16 = fmaxf(m16, __shfl_xor_sync(0xffffffffu, m16, o, 16));
        float e = __expf(v - m16);
        float se = e;
#pragma unroll
        for (int o = 8; o > 0; o >>= 1) se += __shfl_xor_sync(0xffffffffu, se, o, 16);
        if (lane < 16) out[(size_t)row * 16 + lane] = e / se;
    } else {
        const float* arow = adj + (size_t)row * NV;
        float mx = -INFINITY;
        for (int j = lane; j < NV; j += 32) {
            float lv = lrelu(s_i + g_t2[j]);
            if (__ldcs(&arow[j]) == 0.f) lv += NEGV;
            mx = fmaxf(mx, lv);
        }
#pragma unroll
        for (int o = 16; o > 0; o >>= 1) mx = fmaxf(mx, __shfl_xor_sync(0xffffffffu, mx, o));
        float sum = 0.f;
        for (int j = lane; j < NV; j += 32) {
            float lv = lrelu(s_i + g_t2[j]);
            if (__ldcs(&arow[j]) == 0.f) lv += NEGV;
            sum += __expf(lv - mx);
        }
#pragma unroll
        for (int o = 16; o > 0; o >>= 1) sum += __shfl_xor_sync(0xffffffffu, sum, o);
        int q = lane >> 4, c = lane & 15;
        float acc = 0.f;
        for (int j = q; j < NV; j += 2) {
            float lv = lrelu(s_i + g_t2[j]);
            if (arow[j] == 0.f) lv += NEGV;
            acc += __expf(lv - mx) * __ldg(&g_H2[(size_t)j * 16 + c]);
        }
        acc += __shfl_down_sync(0xffffffffu, acc, 16);
        float v = eluf(acc / sum);
        float m16 = v;
#pragma unroll
        for (int o = 8; o > 0; o >>= 1) m16 = fmaxf(m16, __shfl_xor_sync(0xffffffffu, m16, o, 16));
        float e = __expf(v - m16);
        float se = e;
#pragma unroll
        for (int o = 8; o > 0; o >>= 1) se += __shfl_xor_sync(0xffffffffu, se, o, 16);
        if (lane < 16) out[(size_t)row * 16 + lane] = e / se;
    }
}

// ---------------- launch ----------------
extern "C" void kernel_launch(void* const* d_in, const int* in_sizes, int n_in,
                              void* d_out, int out_size) {
    const float* adj  = (const float*)d_in[0];
    const float* feat = (const float*)d_in[1];
    const float* W0   = (const float*)d_in[2];
    const float* a1_0 = (const float*)d_in[3];
    const float* a2_0 = (const float*)d_in[4];
    const float* Wout = (const float*)d_in[5];
    const float* a1o  = (const float*)d_in[6];
    const float* a2o  = (const float*)d_in[7];
    float* out = (float*)d_out;

    k_prep<<<512, 256>>>(W0, feat);
    k_gemm<<<(NV / 64) * NHEAD, 256>>>(a1_0, a2_0);
    k_attn_hidden<<<NV / ROWS_PER_ATTN_BLOCK, 256>>>(adj, Wout, a1o, a2o);
    k_attn_out<<<NV / ROWS_PER_OUT_BLOCK, 256>>>(adj, out);
}